// round 2
// baseline (speedup 1.0000x reference)
#include <cuda_runtime.h>
#include <math.h>

#define NROWS 65536
#define DIMS  64
#define KCODE 1024
#define BM    128
#define BN    128
#define NT    (KCODE/BN)   // 8
#define TM    8
#define TN    8
#define THREADS 256
#define ES_LD 132          // padded leading dim for code tile (bank-conflict relief)

// output layout (floats): [loss(1) | quantized(4194304) | perplexity(1) | encodings(67108864)]
#define Q_OFF    1
#define Q_SIZE   4194304
#define P_OFF    (Q_OFF + Q_SIZE)          // 4194305
#define ENC_OFF  (P_OFF + 1)               // 4194306

// smem layout (floats):
// xs [DIMS][BM]        = 8192
// es [DIMS][ES_LD]     = 8448
// x2s[BM]              = 128
// e2s[BN]              = 128
// rmin[16][BM]         = 2048
// ridx[16][BM] (int)   = 2048
#define SMEM_FLOATS (DIMS*BM + DIMS*ES_LD + BM + BN + 16*BM + 16*BM)
#define SMEM_BYTES  (SMEM_FLOATS * 4)

__device__ int    g_counts[KCODE];
__device__ double g_loss_sum;

__global__ void vq_init_kernel() {
    int t = blockIdx.x * blockDim.x + threadIdx.x;
    if (t < KCODE) g_counts[t] = 0;
    if (t == 0)    g_loss_sum = 0.0;
}

__global__ __launch_bounds__(THREADS, 2)
void vq_main_kernel(const float* __restrict__ x,
                    const float* __restrict__ cb,
                    float* __restrict__ out) {
    extern __shared__ float smem[];
    float* xs  = smem;                 // [DIMS][BM]
    float* es  = xs + DIMS * BM;       // [DIMS][ES_LD]
    float* x2s = es + DIMS * ES_LD;    // [BM]
    float* e2s = x2s + BM;             // [BN]
    float* rmin = e2s + BN;            // [16][BM]
    int*   ridx = (int*)(rmin + 16 * BM);

    const int tid = threadIdx.x;
    const int n0  = blockIdx.x * BM;       // first flattened row of this CTA
    const int b   = n0 >> 10;              // image index (1024 rows per image)
    const int hw0 = n0 & 1023;             // h*32+w base within image
    const float* xb = x + (size_t)b * 65536 + hw0;

    // ---- load x tile: xs[c][r] = x[b, c, hw0+r]  (coalesced over r) ----
    #pragma unroll
    for (int i = 0; i < (DIMS * BM) / THREADS; i++) {  // 32
        int idx = tid + i * THREADS;
        int c = idx >> 7;          // /128
        int r = idx & 127;
        xs[c * BM + r] = xb[c * 1024 + r];
    }
    __syncthreads();

    // ---- row norms ||x||^2 ----
    if (tid < BM) {
        float s = 0.f;
        #pragma unroll
        for (int c = 0; c < DIMS; c++) {
            float v = xs[c * BM + tid];
            s = fmaf(v, v, s);
        }
        x2s[tid] = s;
    }

    const int ty = tid >> 4;   // 0..15  (rows)
    const int tx = tid & 15;   // 0..15  (codes)

    float best[TM];
    int   bidx[TM];
    #pragma unroll
    for (int i = 0; i < TM; i++) { best[i] = 3.4e38f; bidx[i] = 0; }

    for (int ct = 0; ct < NT; ct++) {
        __syncthreads();  // protect es reuse across tiles (and x2s on first iter)
        const int k0 = ct * BN;
        // ---- load code tile transposed: es[c][kl] = cb[k0+kl, c] ----
        #pragma unroll
        for (int i = 0; i < (BN * DIMS) / THREADS; i++) {  // 32
            int idx = tid + i * THREADS;
            int kl = idx >> 6;    // /64
            int c  = idx & 63;
            es[c * ES_LD + kl] = cb[(size_t)(k0 + kl) * DIMS + c];
        }
        __syncthreads();
        if (tid < BN) {
            float s = 0.f;
            #pragma unroll
            for (int c = 0; c < DIMS; c++) {
                float v = es[c * ES_LD + tid];
                s = fmaf(v, v, s);
            }
            e2s[tid] = s;
        }
        __syncthreads();

        // ---- 128x128 GEMM micro-tile: 8x8 per thread, K=64 ----
        float acc[TM][TN];
        #pragma unroll
        for (int i = 0; i < TM; i++)
            #pragma unroll
            for (int j = 0; j < TN; j++) acc[i][j] = 0.f;

        #pragma unroll 8
        for (int c = 0; c < DIMS; c++) {
            float4 a0 = *(const float4*)&xs[c * BM + ty * TM];
            float4 a1 = *(const float4*)&xs[c * BM + ty * TM + 4];
            float4 b0 = *(const float4*)&es[c * ES_LD + tx * TN];
            float4 b1 = *(const float4*)&es[c * ES_LD + tx * TN + 4];
            float av[8] = {a0.x, a0.y, a0.z, a0.w, a1.x, a1.y, a1.z, a1.w};
            float bv[8] = {b0.x, b0.y, b0.z, b0.w, b1.x, b1.y, b1.z, b1.w};
            #pragma unroll
            for (int i = 0; i < TM; i++)
                #pragma unroll
                for (int j = 0; j < TN; j++)
                    acc[i][j] = fmaf(av[i], bv[j], acc[i][j]);
        }

        // ---- running argmin update (distance mirrors reference rounding) ----
        #pragma unroll
        for (int i = 0; i < TM; i++) {
            float xi2 = x2s[ty * TM + i];
            #pragma unroll
            for (int j = 0; j < TN; j++) {
                float d = fmaf(-2.f, acc[i][j], xi2) + e2s[tx * TN + j];
                int kk = k0 + tx * TN + j;
                if (d < best[i]) { best[i] = d; bidx[i] = kk; }
            }
        }
    }

    // ---- cross-thread (tx) argmin reduce with lowest-index tie-break ----
    #pragma unroll
    for (int i = 0; i < TM; i++) {
        rmin[tx * BM + ty * TM + i] = best[i];
        ridx[tx * BM + ty * TM + i] = bidx[i];
    }
    __syncthreads();
    if (tid < BM) {
        float dmin = rmin[tid];
        int   kmin = ridx[tid];
        #pragma unroll
        for (int t = 1; t < 16; t++) {
            float v  = rmin[t * BM + tid];
            int   kv = ridx[t * BM + tid];
            if (v < dmin || (v == dmin && kv < kmin)) { dmin = v; kmin = kv; }
        }
        rmin[tid] = dmin;   // final per-row min distance
        ridx[tid] = kmin;   // final per-row index
        atomicAdd(&g_counts[kmin], 1);
    }
    __syncthreads();

    // ---- loss partial: sum of min distances (== sum (q - x)^2 per row) ----
    if (tid == 0) {
        double s = 0.0;
        for (int r = 0; r < BM; r++) s += (double)rmin[r];
        atomicAdd(&g_loss_sum, s);
    }

    // ---- quantized output (NCHW), coalesced over r ----
    float* qout = out + Q_OFF;
    #pragma unroll
    for (int i = 0; i < (BM * DIMS) / THREADS; i++) {  // 32
        int idx = tid + i * THREADS;
        int c = idx >> 7;
        int r = idx & 127;
        qout[(size_t)b * 65536 + (size_t)c * 1024 + hw0 + r] =
            cb[(size_t)ridx[r] * DIMS + c];
    }

    // ---- encodings: zero-fill + one-hot (region base only 8B aligned -> float2) ----
    {
        float2* enc = (float2*)(out + ENC_OFF + (size_t)n0 * KCODE);
        const float2 z = {0.f, 0.f};
        const int total2 = BM * KCODE / 2;   // 65536
        for (int i = tid; i < total2; i += THREADS) enc[i] = z;
        __syncthreads();
        if (tid < BM)
            out[ENC_OFF + (size_t)(n0 + tid) * KCODE + ridx[tid]] = 1.0f;
    }
}

__global__ void vq_finalize_kernel(float* __restrict__ out) {
    __shared__ double red[32];
    int t = threadIdx.x;  // 1024 threads, one per code
    float p = (float)g_counts[t] / 65536.f;
    double term = (double)p * log((double)p + 1e-10);
    #pragma unroll
    for (int o = 16; o > 0; o >>= 1)
        term += __shfl_down_sync(0xffffffffu, term, o);
    if ((t & 31) == 0) red[t >> 5] = term;
    __syncthreads();
    if (t < 32) {
        double v = red[t];
        #pragma unroll
        for (int o = 16; o > 0; o >>= 1)
            v += __shfl_down_sync(0xffffffffu, v, o);
        if (t == 0) {
            out[P_OFF] = (float)exp(-v);                           // perplexity
            out[0]     = (float)(1.25 * g_loss_sum / 4194304.0);   // loss = (1+0.25)*mse
        }
    }
}

extern "C" void kernel_launch(void* const* d_in, const int* in_sizes, int n_in,
                              void* d_out, int out_size) {
    const float* x  = (const float*)d_in[0];
    const float* cb = (const float*)d_in[1];
    float* out = (float*)d_out;

    cudaFuncSetAttribute(vq_main_kernel,
                         cudaFuncAttributeMaxDynamicSharedMemorySize, SMEM_BYTES);

    vq_init_kernel<<<4, 256>>>();
    vq_main_kernel<<<NROWS / BM, THREADS, SMEM_BYTES>>>(x, cb, out);
    vq_finalize_kernel<<<1, 1024>>>(out);
}

// round 3
// speedup vs baseline: 1.0388x; 1.0388x over previous
#include <cuda_runtime.h>
#include <math.h>

#define NROWS 65536
#define DIMS  64
#define KCODE 1024
#define BM    128
#define BN    128
#define NT    (KCODE/BN)   // 8
#define TM    8
#define TN    8
#define THREADS 256
#define ES_LD 132          // padded leading dim for code tile (bank-conflict relief)

// output layout (floats): [loss(1) | quantized(4194304) | perplexity(1) | encodings(67108864)]
#define Q_OFF    1
#define Q_SIZE   4194304
#define P_OFF    (Q_OFF + Q_SIZE)          // 4194305
#define ENC_OFF  (P_OFF + 1)               // 4194306

#define SMEM_FLOATS (DIMS*BM + DIMS*ES_LD + BM + BN + 16*BM + 16*BM)
#define SMEM_BYTES  (SMEM_FLOATS * 4)

// packed fp32x2 helpers (Blackwell FFMA2 — ptxas never emits these from C++)
#define FMA2(d, a, b, c) \
    asm("fma.rn.f32x2 %0, %1, %2, %3;" : "=l"(d) : "l"(a), "l"(b), "l"(c))
#define ADD2(d, a, b) \
    asm("add.rn.f32x2 %0, %1, %2;" : "=l"(d) : "l"(a), "l"(b))
#define DUP2(d, s) \
    asm("mov.b64 %0, {%1, %1};" : "=l"(d) : "f"(s))
#define UNPACK2(lo, hi, s) \
    asm("mov.b64 {%0, %1}, %2;" : "=f"(lo), "=f"(hi) : "l"(s))

__device__ int    g_counts[KCODE];   // zero at module load; finalize re-zeroes
__device__ double g_loss_sum;        // ditto

__global__ __launch_bounds__(THREADS, 2)
void vq_main_kernel(const float* __restrict__ x,
                    const float* __restrict__ cb,
                    float* __restrict__ out) {
    extern __shared__ float smem[];
    float* xs  = smem;                 // [DIMS][BM]
    float* es  = xs + DIMS * BM;       // [DIMS][ES_LD]
    float* x2s = es + DIMS * ES_LD;    // [BM]
    float* e2s = x2s + BM;             // [BN]
    float* rmin = e2s + BN;            // [16][BM]
    int*   ridx = (int*)(rmin + 16 * BM);

    const int tid = threadIdx.x;
    const int n0  = blockIdx.x * BM;       // first flattened row of this CTA
    const int b   = n0 >> 10;              // image index (1024 rows per image)
    const int hw0 = n0 & 1023;             // h*32+w base within image
    const float* xb = x + (size_t)b * 65536 + hw0;

    // ---- load x tile: xs[c][r] = x[b, c, hw0+r]  (coalesced over r) ----
    #pragma unroll
    for (int i = 0; i < (DIMS * BM) / THREADS; i++) {  // 32
        int idx = tid + i * THREADS;
        int c = idx >> 7;
        int r = idx & 127;
        xs[c * BM + r] = xb[c * 1024 + r];
    }
    __syncthreads();

    // ---- row norms ||x||^2 ----
    if (tid < BM) {
        float s = 0.f;
        #pragma unroll
        for (int c = 0; c < DIMS; c++) {
            float v = xs[c * BM + tid];
            s = fmaf(v, v, s);
        }
        x2s[tid] = s;
    }

    const int ty = tid >> 4;   // 0..15  (row groups of 8)
    const int tx = tid & 15;   // 0..15  (code groups of 8)

    float best[TM];
    int   bidx[TM];
    #pragma unroll
    for (int i = 0; i < TM; i++) { best[i] = 3.4e38f; bidx[i] = 0; }

    unsigned long long neg2dup;
    DUP2(neg2dup, -2.0f);

    for (int ct = 0; ct < NT; ct++) {
        __syncthreads();  // protect es reuse across tiles (and x2s on first iter)
        const int k0 = ct * BN;
        // ---- load code tile transposed: es[c][kl] = cb[k0+kl, c] ----
        #pragma unroll
        for (int i = 0; i < (BN * DIMS) / THREADS; i++) {  // 32
            int idx = tid + i * THREADS;
            int kl = idx >> 6;
            int c  = idx & 63;
            es[c * ES_LD + kl] = cb[(size_t)(k0 + kl) * DIMS + c];
        }
        __syncthreads();
        if (tid < BN) {
            float s = 0.f;
            #pragma unroll
            for (int c = 0; c < DIMS; c++) {
                float v = es[c * ES_LD + tid];
                s = fmaf(v, v, s);
            }
            e2s[tid] = s;
        }
        __syncthreads();

        // ---- 128x128 tile, 8x8 per thread, K=64; accumulators packed f32x2
        //      along rows (lane0 = row 2*i2, lane1 = row 2*i2+1)             ----
        unsigned long long acc2[TM/2][TN];
        #pragma unroll
        for (int i = 0; i < TM/2; i++)
            #pragma unroll
            for (int j = 0; j < TN; j++) acc2[i][j] = 0ULL;

        #pragma unroll 8
        for (int c = 0; c < DIMS; c++) {
            // A: 8 consecutive rows -> 4 packed pairs, loaded directly as 64-bit
            ulonglong2 A0 = *(const ulonglong2*)&xs[c * BM + ty * TM];
            ulonglong2 A1 = *(const ulonglong2*)&xs[c * BM + ty * TM + 4];
            unsigned long long av[4] = {A0.x, A0.y, A1.x, A1.y};
            // B: 8 codes, each duplicated into both lanes
            float4 B0 = *(const float4*)&es[c * ES_LD + tx * TN];
            float4 B1 = *(const float4*)&es[c * ES_LD + tx * TN + 4];
            unsigned long long bd[8];
            DUP2(bd[0], B0.x); DUP2(bd[1], B0.y); DUP2(bd[2], B0.z); DUP2(bd[3], B0.w);
            DUP2(bd[4], B1.x); DUP2(bd[5], B1.y); DUP2(bd[6], B1.z); DUP2(bd[7], B1.w);
            #pragma unroll
            for (int i = 0; i < TM/2; i++)
                #pragma unroll
                for (int j = 0; j < TN; j++)
                    FMA2(acc2[i][j], av[i], bd[j], acc2[i][j]);
        }

        // ---- running argmin update (per-lane rounding mirrors reference) ----
        #pragma unroll
        for (int i2 = 0; i2 < TM/2; i2++) {
            unsigned long long x2p = *(const unsigned long long*)&x2s[ty * TM + 2 * i2];
            #pragma unroll
            for (int j = 0; j < TN; j++) {
                unsigned long long e2d, t, d2;
                DUP2(e2d, e2s[tx * TN + j]);
                FMA2(t, neg2dup, acc2[i2][j], x2p);   // -2*acc + x2 (one rounding)
                ADD2(d2, t, e2d);                     // + e2
                float dlo, dhi;
                UNPACK2(dlo, dhi, d2);
                int kk = k0 + tx * TN + j;
                if (dlo < best[2 * i2])     { best[2 * i2]     = dlo; bidx[2 * i2]     = kk; }
                if (dhi < best[2 * i2 + 1]) { best[2 * i2 + 1] = dhi; bidx[2 * i2 + 1] = kk; }
            }
        }
    }

    // ---- cross-thread (tx) argmin reduce with lowest-index tie-break ----
    #pragma unroll
    for (int i = 0; i < TM; i++) {
        rmin[tx * BM + ty * TM + i] = best[i];
        ridx[tx * BM + ty * TM + i] = bidx[i];
    }
    __syncthreads();
    if (tid < BM) {
        float dmin = rmin[tid];
        int   kmin = ridx[tid];
        #pragma unroll
        for (int t = 1; t < 16; t++) {
            float v  = rmin[t * BM + tid];
            int   kv = ridx[t * BM + tid];
            if (v < dmin || (v == dmin && kv < kmin)) { dmin = v; kmin = kv; }
        }
        rmin[tid] = dmin;   // final per-row min distance
        ridx[tid] = kmin;   // final per-row index
        atomicAdd(&g_counts[kmin], 1);
    }
    __syncthreads();

    // ---- loss partial: sum of min distances ----
    if (tid == 0) {
        double s = 0.0;
        for (int r = 0; r < BM; r++) s += (double)rmin[r];
        atomicAdd(&g_loss_sum, s);
    }

    // ---- quantized output (NCHW), coalesced over r ----
    float* qout = out + Q_OFF;
    #pragma unroll
    for (int i = 0; i < (BM * DIMS) / THREADS; i++) {  // 32
        int idx = tid + i * THREADS;
        int c = idx >> 7;
        int r = idx & 127;
        qout[(size_t)b * 65536 + (size_t)c * 1024 + hw0 + r] =
            cb[(size_t)ridx[r] * DIMS + c];
    }

    // ---- encodings: zero-fill (STG.128 body, float2 head/tail) + one-hot ----
    {
        float* encb = out + ENC_OFF + (size_t)n0 * KCODE;   // 8B-aligned, 16B+8
        if (tid == 0) *(float2*)encb = make_float2(0.f, 0.f);
        float4* enc4 = (float4*)(encb + 2);
        const int n4 = (BM * KCODE - 4) / 4;                // 32767
        const float4 z4 = make_float4(0.f, 0.f, 0.f, 0.f);
        for (int i = tid; i < n4; i += THREADS) enc4[i] = z4;
        if (tid == THREADS - 1)
            *(float2*)(encb + BM * KCODE - 2) = make_float2(0.f, 0.f);
        __syncthreads();
        if (tid < BM)
            out[ENC_OFF + (size_t)(n0 + tid) * KCODE + ridx[tid]] = 1.0f;
    }
}

__global__ void vq_finalize_kernel(float* __restrict__ out) {
    __shared__ double red[32];
    int t = threadIdx.x;  // 1024 threads, one per code
    int cnt = g_counts[t];
    g_counts[t] = 0;                       // leave state zeroed for next launch
    float p = (float)cnt / 65536.f;
    double term = (double)p * log((double)p + 1e-10);
    #pragma unroll
    for (int o = 16; o > 0; o >>= 1)
        term += __shfl_down_sync(0xffffffffu, term, o);
    if ((t & 31) == 0) red[t >> 5] = term;
    __syncthreads();
    if (t < 32) {
        double v = red[t];
        #pragma unroll
        for (int o = 16; o > 0; o >>= 1)
            v += __shfl_down_sync(0xffffffffu, v, o);
        if (t == 0) {
            out[P_OFF] = (float)exp(-v);                           // perplexity
            out[0]     = (float)(1.25 * g_loss_sum / 4194304.0);   // loss
            g_loss_sum = 0.0;              // reset for next launch
        }
    }
}

extern "C" void kernel_launch(void* const* d_in, const int* in_sizes, int n_in,
                              void* d_out, int out_size) {
    const float* x  = (const float*)d_in[0];
    const float* cb = (const float*)d_in[1];
    float* out = (float*)d_out;

    cudaFuncSetAttribute(vq_main_kernel,
                         cudaFuncAttributeMaxDynamicSharedMemorySize, SMEM_BYTES);

    vq_main_kernel<<<NROWS / BM, THREADS, SMEM_BYTES>>>(x, cb, out);
    vq_finalize_kernel<<<1, 1024>>>(out);
}

// round 5
// speedup vs baseline: 1.3521x; 1.3016x over previous
#include <cuda_runtime.h>
#include <cuda_bf16.h>
#include <math.h>
#include <stdint.h>

#define NROWS 65536
#define DIMS  64
#define KCODE 1024
#define BM    128
#define THREADS 256
#define NCHUNK 32           // 32 chunks of 32 codes
#define CHW    32           // codes per chunk

// output layout (floats): [loss(1) | quantized(4194304) | perplexity(1) | encodings(67108864)]
#define Q_OFF    1
#define Q_SIZE   4194304
#define P_OFF    (Q_OFF + Q_SIZE)
#define ENC_OFF  (P_OFF + 1)

// padded bf16 row stride: 72 elems = 144 bytes (16B aligned, conflict-free ldmatrix)
#define LDB   72
#define LDBB  144

// smem byte offsets
#define A_OFF    0                       // 3 images x 128 x 144B = 55296
#define B_OFF    55296                   // 3 images x 32 x 144B  = 13824
#define E2_OFF   69120                   // 1024 f32 = 4096
#define X2_OFF   73216                   // 128 f32  = 512
#define RMIN_OFF 73728                   // 128 f32
#define RIDX_OFF 74240                   // 128 i32
#define SMEM_BYTES 74752

__device__ __nv_bfloat16 g_cbs[3 * KCODE * LDB];  // padded split images
__device__ float  g_e2[KCODE];
__device__ int    g_counts[KCODE];   // zero at load; finalize re-zeroes
__device__ double g_loss_sum;

__device__ __forceinline__ uint32_t smem_u32(const void* p) {
    uint32_t a;
    asm("{ .reg .u64 t; cvta.to.shared.u64 t, %1; cvt.u32.u64 %0, t; }" : "=r"(a) : "l"(p));
    return a;
}
#define LDSM_X4(r0, r1, r2, r3, addr) \
    asm volatile("ldmatrix.sync.aligned.m8n8.x4.shared.b16 {%0,%1,%2,%3}, [%4];" \
                 : "=r"(r0), "=r"(r1), "=r"(r2), "=r"(r3) : "r"(addr))
#define LDSM_X2(r0, r1, addr) \
    asm volatile("ldmatrix.sync.aligned.m8n8.x2.shared.b16 {%0,%1}, [%2];" \
                 : "=r"(r0), "=r"(r1) : "r"(addr))
#define MMA_BF16(c0, c1, c2, c3, a0, a1, a2, a3, b0, b1) \
    asm volatile("mma.sync.aligned.m16n8k16.row.col.f32.bf16.bf16.f32 " \
                 "{%0,%1,%2,%3}, {%4,%5,%6,%7}, {%8,%9}, {%0,%1,%2,%3};" \
                 : "+f"(c0), "+f"(c1), "+f"(c2), "+f"(c3) \
                 : "r"(a0), "r"(a1), "r"(a2), "r"(a3), "r"(b0), "r"(b1))

// ---------------- prologue: split codebook into 3 padded bf16 images + e2 ----------------
__global__ void vq_prep_kernel(const float* __restrict__ cb) {
    int k = blockIdx.x * 128 + threadIdx.x;   // code 0..1023
    float e2 = 0.f;
    for (int c = 0; c < DIMS; c++) {
        float v = cb[k * DIMS + c];
        e2 = fmaf(v, v, e2);
        __nv_bfloat16 h = __float2bfloat16(v);
        float r1 = v - __bfloat162float(h);
        __nv_bfloat16 m = __float2bfloat16(r1);
        float r2 = r1 - __bfloat162float(m);
        __nv_bfloat16 l = __float2bfloat16(r2);
        g_cbs[0 * KCODE * LDB + k * LDB + c] = h;
        g_cbs[1 * KCODE * LDB + k * LDB + c] = m;
        g_cbs[2 * KCODE * LDB + k * LDB + c] = l;
    }
    g_e2[k] = e2;
}

// ---------------- main fused kernel ----------------
__global__ __launch_bounds__(THREADS, 2)
void vq_main_kernel(const float* __restrict__ x,
                    const float* __restrict__ cb,
                    float* __restrict__ out) {
    extern __shared__ char smem[];
    const uint32_t su = smem_u32(smem);
    float* e2s  = (float*)(smem + E2_OFF);
    float* x2s  = (float*)(smem + X2_OFF);
    float* rmin = (float*)(smem + RMIN_OFF);
    int*   ridx = (int*)(smem + RIDX_OFF);

    const int tid  = threadIdx.x;
    const int wid  = tid >> 5;
    const int lane = tid & 31;
    const int n0   = blockIdx.x * BM;
    const int b    = n0 >> 10;
    const int hw0  = n0 & 1023;
    const float* xb = x + (size_t)b * 65536 + hw0;

    // ---- setup: x 3-way split (tid<128: one row each) / e2 preload (tid>=128) ----
    if (tid < BM) {
        int r = tid;
        float s = 0.f;
        for (int c = 0; c < DIMS; c++) {
            float v = xb[c * 1024 + r];
            s = fmaf(v, v, s);
            __nv_bfloat16 h = __float2bfloat16(v);
            float r1 = v - __bfloat162float(h);
            __nv_bfloat16 m = __float2bfloat16(r1);
            float r2 = r1 - __bfloat162float(m);
            __nv_bfloat16 l = __float2bfloat16(r2);
            *(__nv_bfloat16*)(smem + A_OFF + 0 * 18432 + r * LDBB + c * 2) = h;
            *(__nv_bfloat16*)(smem + A_OFF + 1 * 18432 + r * LDBB + c * 2) = m;
            *(__nv_bfloat16*)(smem + A_OFF + 2 * 18432 + r * LDBB + c * 2) = l;
        }
        x2s[r] = s;
    } else {
        #pragma unroll
        for (int i = tid - 128; i < KCODE; i += 128) e2s[i] = g_e2[i];
    }
    __syncthreads();

    // ---- load A fragments once: 3 images x 4 k-steps, ldmatrix.x4 ----
    uint32_t af[3][4][4];
    {
        int row = wid * 16 + (lane & 15);
        int kh  = (lane >> 4) & 1;
        #pragma unroll
        for (int q = 0; q < 3; q++)
            #pragma unroll
            for (int ks = 0; ks < 4; ks++) {
                uint32_t a = su + A_OFF + q * 18432 + row * LDBB + ks * 32 + kh * 16;
                LDSM_X4(af[q][ks][0], af[q][ks][1], af[q][ks][2], af[q][ks][3], a);
            }
    }

    const float x2_0 = x2s[wid * 16 + (lane >> 2)];
    const float x2_1 = x2s[wid * 16 + (lane >> 2) + 8];
    float best0 = 3.4e38f, best1 = 3.4e38f;
    int   bidx0 = 0,       bidx1 = 0;

    float* encb = out + ENC_OFF + (size_t)n0 * KCODE;   // 8B-aligned
    float4* enc4 = (float4*)(encb + 2);                 // 32767-float4 body
    if (tid == 0) *(float2*)encb = make_float2(0.f, 0.f);
    if (tid == 1) *(float2*)(encb + (size_t)BM * KCODE - 2) = make_float2(0.f, 0.f);

    // B-frag lane offset (lanes 16-31 mirror 0-15; harmless for x2)
    const int bl   = lane & 15;
    const int bofs = (bl & 7) * LDBB + (bl >> 3) * 16;

    // product order: (Aq,Bq) = hh, hm, mh, hl, lh, mm
    const int AQ[6] = {0, 0, 1, 0, 2, 1};
    const int BQ[6] = {0, 1, 0, 2, 0, 1};

    for (int nt = 0; nt < NCHUNK; nt++) {
        if (nt) __syncthreads();           // previous chunk's B fully consumed
        // ---- copy B chunk: 3 images x 32 codes x 144B (contiguous per image) ----
        {
            const float4* src = (const float4*)g_cbs;
            float4* dst = (float4*)(smem + B_OFF);
            #pragma unroll
            for (int u = 0; u < 4; u++) {
                int i = tid + u * THREADS;
                if (i < 864) {                       // 3 * 288
                    int q = i / 288, r = i % 288;
                    dst[q * 288 + r] = src[q * (KCODE * LDB / 8) + nt * 288 + r];
                }
            }
        }
        __syncthreads();

        float acc[4][4];
        #pragma unroll
        for (int t = 0; t < 4; t++)
            #pragma unroll
            for (int j = 0; j < 4; j++) acc[t][j] = 0.f;

        #pragma unroll
        for (int ks = 0; ks < 4; ks++) {
            #pragma unroll
            for (int t = 0; t < 4; t++) {           // 4 n-tiles of 8 codes
                uint32_t bb[3][2];
                #pragma unroll
                for (int q = 0; q < 3; q++) {
                    uint32_t a = su + B_OFF + q * 4608 + t * 8 * LDBB + ks * 32 + bofs;
                    LDSM_X2(bb[q][0], bb[q][1], a);
                }
                #pragma unroll
                for (int p = 0; p < 6; p++)
                    MMA_BF16(acc[t][0], acc[t][1], acc[t][2], acc[t][3],
                             af[AQ[p]][ks][0], af[AQ[p]][ks][1],
                             af[AQ[p]][ks][2], af[AQ[p]][ks][3],
                             bb[BQ[p]][0], bb[BQ[p]][1]);
            }
        }

        // ---- fused distance + argmin (ascending code order, strict <) ----
        #pragma unroll
        for (int t = 0; t < 4; t++) {
            int c0 = nt * CHW + t * 8 + (lane & 3) * 2;
            float e2a = e2s[c0], e2b = e2s[c0 + 1];
            float d;
            d = fmaf(-2.f, acc[t][0], x2_0) + e2a;
            if (d < best0) { best0 = d; bidx0 = c0; }
            d = fmaf(-2.f, acc[t][1], x2_0) + e2b;
            if (d < best0) { best0 = d; bidx0 = c0 + 1; }
            d = fmaf(-2.f, acc[t][2], x2_1) + e2a;
            if (d < best1) { best1 = d; bidx1 = c0; }
            d = fmaf(-2.f, acc[t][3], x2_1) + e2b;
            if (d < best1) { best1 = d; bidx1 = c0 + 1; }
        }

        // ---- interleaved encodings zero-fill (1 float4/thread/chunk slice) ----
        #pragma unroll
        for (int u = 0; u < 4; u++) {
            int i = nt * 1024 + u * 256 + tid;
            if (i < 32767) enc4[i] = make_float4(0.f, 0.f, 0.f, 0.f);
        }
    }

    // ---- cross-lane argmin reduce (4 lanes share each row), idx tie-break ----
    #pragma unroll
    for (int off = 1; off < 4; off <<= 1) {
        float ob0 = __shfl_xor_sync(0xffffffffu, best0, off);
        int   oi0 = __shfl_xor_sync(0xffffffffu, bidx0, off);
        if (ob0 < best0 || (ob0 == best0 && oi0 < bidx0)) { best0 = ob0; bidx0 = oi0; }
        float ob1 = __shfl_xor_sync(0xffffffffu, best1, off);
        int   oi1 = __shfl_xor_sync(0xffffffffu, bidx1, off);
        if (ob1 < best1 || (ob1 == best1 && oi1 < bidx1)) { best1 = ob1; bidx1 = oi1; }
    }
    if ((lane & 3) == 0) {
        int r0 = wid * 16 + (lane >> 2);
        rmin[r0] = best0;     ridx[r0] = bidx0;
        rmin[r0 + 8] = best1; ridx[r0 + 8] = bidx1;
    }
    __syncthreads();

    if (tid < BM) atomicAdd(&g_counts[ridx[tid]], 1);

    // ---- loss partial ----
    if (tid == 0) {
        double s = 0.0;
        for (int r = 0; r < BM; r++) s += (double)rmin[r];
        atomicAdd(&g_loss_sum, s);
    }

    // ---- quantized output (NCHW), coalesced over r ----
    float* qout = out + Q_OFF;
    #pragma unroll
    for (int i = 0; i < (BM * DIMS) / THREADS; i++) {  // 32
        int idx = tid + i * THREADS;
        int c = idx >> 7;
        int r = idx & 127;
        qout[(size_t)b * 65536 + (size_t)c * 1024 + hw0 + r] =
            cb[(size_t)ridx[r] * DIMS + c];
    }

    // ---- one-hot writes (zero-fill already complete) ----
    if (tid < BM)
        encb[(size_t)tid * KCODE + ridx[tid]] = 1.0f;
}

__global__ void vq_finalize_kernel(float* __restrict__ out) {
    __shared__ float red[8];
    int t = threadIdx.x;   // 256 threads, 4 codes each
    float acc = 0.f;
    #pragma unroll
    for (int i = 0; i < 4; i++) {
        int k = t + i * 256;
        int cnt = g_counts[k];
        g_counts[k] = 0;
        float p = (float)cnt * (1.f / 65536.f);
        acc += p * logf(p + 1e-10f);
    }
    #pragma unroll
    for (int o = 16; o > 0; o >>= 1)
        acc += __shfl_down_sync(0xffffffffu, acc, o);
    if ((t & 31) == 0) red[t >> 5] = acc;
    __syncthreads();
    if (t == 0) {
        float s = 0.f;
        #pragma unroll
        for (int w = 0; w < 8; w++) s += red[w];
        out[P_OFF] = expf(-s);
        out[0]     = (float)(1.25 * g_loss_sum / 4194304.0);
        g_loss_sum = 0.0;
    }
}

__global__ void vq_nop_kernel() {}   // pads launches/call to 4 so ncu -s 5 lands on main

extern "C" void kernel_launch(void* const* d_in, const int* in_sizes, int n_in,
                              void* d_out, int out_size) {
    const float* x  = (const float*)d_in[0];
    const float* cb = (const float*)d_in[1];
    float* out = (float*)d_out;

    cudaFuncSetAttribute(vq_main_kernel,
                         cudaFuncAttributeMaxDynamicSharedMemorySize, SMEM_BYTES);

    vq_prep_kernel<<<8, 128>>>(cb);
    vq_main_kernel<<<NROWS / BM, THREADS, SMEM_BYTES>>>(x, cb, out);
    vq_finalize_kernel<<<1, 256>>>(out);
    vq_nop_kernel<<<1, 32>>>();
}